// round 3
// baseline (speedup 1.0000x reference)
#include <cuda_runtime.h>
#include <cuda_bf16.h>

#define N3 262144
#define N2 65536
#define N1 16384

// Scratch (allocation-free): intermediate activations
__device__ float g_x8 [N3 * 16];
__device__ float g_x7p[N2 * 16];
__device__ float g_x7 [N2 * 32];
__device__ float g_x6p[N1 * 32];
__device__ float g_x6 [N1 * 64];
__device__ float g_x7d[N2 * 32];
__device__ float g_x8d[N3 * 16];

// Fused quadconv (+optional unpool via SHIFT, +optional ReLU).
// out[i][o] = b[o] + sum_{k=0..8, n=neigh[i*9+k]>=0} sum_c feat[(n>>SHIFT)*CIN+c] * w[o][k*CIN+c]
template <int CIN, int COUT, bool RELU, int SHIFT>
__global__ __launch_bounds__(256)
void conv_k(const float* __restrict__ feat, const int* __restrict__ neigh,
            const float* __restrict__ w, const float* __restrict__ b,
            float* __restrict__ out, int N)
{
    extern __shared__ float sw[];               // [COUT][9*CIN] then bias[COUT]
    const int WSZ = COUT * 9 * CIN;
    for (int idx = threadIdx.x; idx < WSZ + COUT; idx += blockDim.x)
        sw[idx] = (idx < WSZ) ? w[idx] : b[idx - WSZ];
    __syncthreads();

    int i = blockIdx.x * blockDim.x + threadIdx.x;
    if (i >= N) return;

    int nbr[9];
#pragma unroll
    for (int k = 0; k < 9; k++) nbr[k] = neigh[i * 9 + k];

    float acc[COUT];
#pragma unroll
    for (int o = 0; o < COUT; o++) acc[o] = sw[WSZ + o];

#pragma unroll
    for (int k = 0; k < 9; k++) {
        int n = nbr[k];
        if (n < 0) continue;
        int src = n >> SHIFT;
        if (CIN == 1) {
            float f = __ldg(feat + src);
#pragma unroll
            for (int o = 0; o < COUT; o++)
                acc[o] += f * sw[o * 9 + k];
        } else {
            const float4* fr = reinterpret_cast<const float4*>(feat + src * CIN);
#pragma unroll
            for (int c = 0; c < CIN / 4; c++) {
                float4 f = __ldg(fr + c);
#pragma unroll
                for (int o = 0; o < COUT; o++) {
                    const float4 wv = *reinterpret_cast<const float4*>(
                        &sw[o * 9 * CIN + k * CIN + c * 4]);
                    acc[o] += f.x * wv.x;
                    acc[o] += f.y * wv.y;
                    acc[o] += f.z * wv.z;
                    acc[o] += f.w * wv.w;
                }
            }
        }
    }

#pragma unroll
    for (int o = 0; o < COUT; o++) {
        float v = acc[o];
        if (RELU) v = fmaxf(v, 0.0f);
        out[i * COUT + o] = v;
    }
}

// Quadpool: keys are arange -> parent of child i is i>>2, every parent has
// exactly 4 contiguous children; inputs are post-ReLU (>=0) so the -inf->0
// fixup in the reference is a no-op.
template <int C>
__global__ __launch_bounds__(256)
void pool_k(const float* __restrict__ in, float* __restrict__ out, int NP)
{
    int idx = blockIdx.x * blockDim.x + threadIdx.x;
    if (idx >= NP * C) return;
    int p = idx / C, c = idx % C;
    const float* base = in + (p * 4) * C + c;
    float m = fmaxf(fmaxf(base[0], base[C]), fmaxf(base[2 * C], base[3 * C]));
    out[idx] = m;
}

static inline int cdiv(int a, int b) { return (a + b - 1) / b; }

extern "C" void kernel_launch(void* const* d_in, const int* in_sizes, int n_in,
                              void* d_out, int out_size)
{
    const float* features = (const float*)d_in[0];
    // d_in[1..3] = keys3/keys2/keys1 (arange -> unused)
    const int* neighs3 = (const int*)d_in[4];
    const int* neighs2 = (const int*)d_in[5];
    const int* neighs1 = (const int*)d_in[6];
    const float* w_enc1 = (const float*)d_in[7];
    const float* b_enc1 = (const float*)d_in[8];
    const float* w_enc2 = (const float*)d_in[9];
    const float* b_enc2 = (const float*)d_in[10];
    const float* w_enc3 = (const float*)d_in[11];
    const float* b_enc3 = (const float*)d_in[12];
    const float* w_dec1 = (const float*)d_in[13];
    const float* b_dec1 = (const float*)d_in[14];
    const float* w_dec2 = (const float*)d_in[15];
    const float* b_dec2 = (const float*)d_in[16];
    const float* w_head = (const float*)d_in[17];
    const float* b_head = (const float*)d_in[18];
    float* out = (float*)d_out;

    float *x8, *x7p, *x7, *x6p, *x6, *x7d, *x8d;
    cudaGetSymbolAddress((void**)&x8,  g_x8);
    cudaGetSymbolAddress((void**)&x7p, g_x7p);
    cudaGetSymbolAddress((void**)&x7,  g_x7);
    cudaGetSymbolAddress((void**)&x6p, g_x6p);
    cudaGetSymbolAddress((void**)&x6,  g_x6);
    cudaGetSymbolAddress((void**)&x7d, g_x7d);
    cudaGetSymbolAddress((void**)&x8d, g_x8d);

    // Two layers need >48KB dynamic shared for the weight stage.
    cudaFuncSetAttribute(conv_k<32, 64, true, 0>,
                         cudaFuncAttributeMaxDynamicSharedMemorySize, 75000);
    cudaFuncSetAttribute(conv_k<64, 32, true, 2>,
                         cudaFuncAttributeMaxDynamicSharedMemorySize, 75000);

    const int T = 256;

    // enc1: [N3,1] -> [N3,16]
    conv_k<1, 16, true, 0><<<cdiv(N3, T), T, (16 * 9 + 16) * 4>>>(
        features, neighs3, w_enc1, b_enc1, x8, N3);
    // pool 3->2
    pool_k<16><<<cdiv(N2 * 16, T), T>>>(x8, x7p, N2);
    // enc2: [N2,16] -> [N2,32]
    conv_k<16, 32, true, 0><<<cdiv(N2, T), T, (32 * 144 + 32) * 4>>>(
        x7p, neighs2, w_enc2, b_enc2, x7, N2);
    // pool 2->1
    pool_k<32><<<cdiv(N1 * 32, T), T>>>(x7, x6p, N1);
    // enc3: [N1,32] -> [N1,64]
    conv_k<32, 64, true, 0><<<cdiv(N1, T), T, (64 * 288 + 64) * 4>>>(
        x6p, neighs1, w_enc3, b_enc3, x6, N1);
    // dec1 with fused unpool (gather parent n>>2): [N2, 9*64] -> [N2,32]
    conv_k<64, 32, true, 2><<<cdiv(N2, T), T, (32 * 576 + 32) * 4>>>(
        x6, neighs2, w_dec1, b_dec1, x7d, N2);
    // dec2 with fused unpool: [N3, 9*32] -> [N3,16]
    conv_k<32, 16, true, 2><<<cdiv(N3, T), T, (16 * 288 + 16) * 4>>>(
        x7d, neighs3, w_dec2, b_dec2, x8d, N3);
    // head: [N3, 9*16] -> [N3,1], no relu
    conv_k<16, 1, false, 0><<<cdiv(N3, T), T, (1 * 144 + 1) * 4>>>(
        x8d, neighs3, w_head, b_head, out, N3);
}

// round 5
// speedup vs baseline: 1.7228x; 1.7228x over previous
#include <cuda_runtime.h>

#define N3 262144
#define N2 65536
#define N1 16384

typedef unsigned long long u64;

// ---------------- scratch (allocation-free) ----------------
__device__ float g_x8 [N3 * 16];
__device__ float g_x7p[N2 * 16];
__device__ float g_x7 [N2 * 32];
__device__ float g_x6p[N1 * 32];
__device__ float g_x6 [N1 * 64];
__device__ float g_x7d[N2 * 32];
__device__ float g_x8d[N3 * 16];
__device__ float g_P  [N2 * 288];   // 75MB, reused by every P phase (max = enc2)

__device__ __forceinline__ u64 pack2(float lo, float hi) {
    u64 r; asm("mov.b64 %0, {%1, %2};" : "=l"(r) : "f"(lo), "f"(hi)); return r;
}
__device__ __forceinline__ void fma2(u64& d, u64 a, u64 b) {
    asm("fma.rn.f32x2 %0, %1, %2, %0;" : "+l"(d) : "l"(a), "l"(b));
}

// ---------------- GEMM: P[M x Ntot] = A[M x K] @ B[K x Ntot] ----------------
// B[c][g] = w[g%COUT][(g/COUT)*K + c]   (per-tap weight transpose, built in smem)
// Tile: TM=128 rows x TN=144 cols, 288 threads, 8x8 per thread (f32x2 packed cols).
template<int K, int COUT>
__global__ __launch_bounds__(288)
void gemm_k(const float* __restrict__ A, const float* __restrict__ w,
            float* __restrict__ P, int Ntot)
{
    extern __shared__ u64 sm64[];
    u64*   As2 = sm64;                       // [K][128] duplicated pairs (a,a)
    float* Bs  = (float*)(sm64 + K * 128);   // [K][144]

    const int tid  = threadIdx.x;
    const int row0 = blockIdx.x * 128;
    const int col0 = blockIdx.y * 144;

    // Stage A transposed + duplicated: As2[c][r] = (A[row0+r][c], same)
    const float4* A4 = reinterpret_cast<const float4*>(A);
    const int KC4 = K / 4;
    for (int idx = tid; idx < 128 * KC4; idx += 288) {
        int r = idx / KC4, c4 = idx % KC4;
        float4 v = A4[(size_t)(row0 + r) * KC4 + c4];
        As2[(c4 * 4 + 0) * 128 + r] = pack2(v.x, v.x);
        As2[(c4 * 4 + 1) * 128 + r] = pack2(v.y, v.y);
        As2[(c4 * 4 + 2) * 128 + r] = pack2(v.z, v.z);
        As2[(c4 * 4 + 3) * 128 + r] = pack2(v.w, v.w);
    }
    // Stage B with on-the-fly transpose of w
    for (int idx = tid; idx < K * 144; idx += 288) {
        int c = idx / 144, cl = idx % 144;
        int g = col0 + cl;
        Bs[c * 144 + cl] = w[(g % COUT) * (9 * K) + (g / COUT) * K + c];
    }
    __syncthreads();

    const int tx = tid % 18;   // 18 col-groups of 8
    const int ty = tid / 18;   // 16 row-groups of 8

    u64 acc[8][4];
#pragma unroll
    for (int r = 0; r < 8; r++)
#pragma unroll
        for (int j = 0; j < 4; j++) acc[r][j] = 0ull;

#pragma unroll 4
    for (int kk = 0; kk < K; kk++) {
        const ulonglong2* ap = reinterpret_cast<const ulonglong2*>(&As2[kk * 128 + ty * 8]);
        ulonglong2 A0 = ap[0], A1 = ap[1], A2 = ap[2], A3 = ap[3];
        u64 a2[8] = {A0.x, A0.y, A1.x, A1.y, A2.x, A2.y, A3.x, A3.y};
        const ulonglong2* bp = reinterpret_cast<const ulonglong2*>(&Bs[kk * 144 + tx * 8]);
        ulonglong2 B0 = bp[0], B1 = bp[1];
        u64 b2[4] = {B0.x, B0.y, B1.x, B1.y};
#pragma unroll
        for (int r = 0; r < 8; r++)
#pragma unroll
            for (int j = 0; j < 4; j++)
                fma2(acc[r][j], a2[r], b2[j]);
    }

#pragma unroll
    for (int r = 0; r < 8; r++) {
        float* dst = P + (size_t)(row0 + ty * 8 + r) * Ntot + col0 + tx * 8;
        *reinterpret_cast<ulonglong2*>(dst)     = make_ulonglong2(acc[r][0], acc[r][1]);
        *reinterpret_cast<ulonglong2*>(dst + 4) = make_ulonglong2(acc[r][2], acc[r][3]);
    }
}

// ---------------- gather-sum: out[i] = relu(b + sum_k P[n_k>>SHIFT][k*COUT..]) --------
template<int COUT, int SHIFT, bool RELU>
__global__ __launch_bounds__(256)
void gather_k(const float* __restrict__ P, const int* __restrict__ neigh,
              const float* __restrict__ b, float* __restrict__ out, int N)
{
    int i = blockIdx.x * 256 + threadIdx.x;
    if (i >= N) return;

    float4 acc[COUT / 4];
#pragma unroll
    for (int j = 0; j < COUT / 4; j++)
        acc[j] = __ldg(reinterpret_cast<const float4*>(b) + j);

#pragma unroll
    for (int k = 0; k < 9; k++) {
        int n = __ldg(neigh + i * 9 + k);
        if (n < 0) continue;
        const float4* p = reinterpret_cast<const float4*>(
            P + (size_t)(n >> SHIFT) * (9 * COUT) + k * COUT);
#pragma unroll
        for (int j = 0; j < COUT / 4; j++) {
            float4 v = __ldg(p + j);
            acc[j].x += v.x; acc[j].y += v.y; acc[j].z += v.z; acc[j].w += v.w;
        }
    }

    float4* o = reinterpret_cast<float4*>(out + (size_t)i * COUT);
#pragma unroll
    for (int j = 0; j < COUT / 4; j++) {
        float4 v = acc[j];
        if (RELU) {
            v.x = fmaxf(v.x, 0.f); v.y = fmaxf(v.y, 0.f);
            v.z = fmaxf(v.z, 0.f); v.w = fmaxf(v.w, 0.f);
        }
        o[j] = v;
    }
}

// ---------------- enc1: CIN=1 direct conv ----------------
__global__ __launch_bounds__(256)
void enc1_k(const float* __restrict__ feat, const int* __restrict__ neigh,
            const float* __restrict__ w, const float* __restrict__ b,
            float* __restrict__ out)
{
    __shared__ float sw[160];   // 144 weights + 16 bias
    if (threadIdx.x < 144) sw[threadIdx.x] = w[threadIdx.x];
    else if (threadIdx.x < 160) sw[threadIdx.x] = b[threadIdx.x - 144];
    __syncthreads();

    int i = blockIdx.x * 256 + threadIdx.x;
    float f[9];
#pragma unroll
    for (int k = 0; k < 9; k++) {
        int n = __ldg(neigh + i * 9 + k);
        f[k] = (n >= 0) ? __ldg(feat + n) : 0.f;
    }
#pragma unroll
    for (int o = 0; o < 16; o++) {
        float a = sw[144 + o];
#pragma unroll
        for (int k = 0; k < 9; k++) a += f[k] * sw[o * 9 + k];
        out[i * 16 + o] = fmaxf(a, 0.f);
    }
}

// ---------------- pool: parent i = child (4i..4i+3) max (keys are arange) ----------
template<int C>
__global__ __launch_bounds__(256)
void pool_k(const float* __restrict__ in, float* __restrict__ out, int NP)
{
    int idx = blockIdx.x * 256 + threadIdx.x;
    if (idx >= NP * C) return;
    int p = idx / C, c = idx % C;
    const float* base = in + (size_t)(p * 4) * C + c;
    out[idx] = fmaxf(fmaxf(base[0], base[C]), fmaxf(base[2 * C], base[3 * C]));
}

// ---------------- head: P6[i][k] = dot(x8d[i], w_head[k*16..]); then scalar gather ----
__global__ __launch_bounds__(256)
void head_p(const float* __restrict__ x, const float* __restrict__ w,
            float* __restrict__ P)
{
    __shared__ float sw[144];
    if (threadIdx.x < 144) sw[threadIdx.x] = w[threadIdx.x];
    __syncthreads();

    int i = blockIdx.x * 256 + threadIdx.x;
    const float4* xr = reinterpret_cast<const float4*>(x + (size_t)i * 16);
    float4 f[4];
#pragma unroll
    for (int j = 0; j < 4; j++) f[j] = __ldg(xr + j);

#pragma unroll
    for (int k = 0; k < 9; k++) {
        float a = 0.f;
#pragma unroll
        for (int j = 0; j < 4; j++) {
            const float4* wv = reinterpret_cast<const float4*>(&sw[k * 16 + j * 4]);
            a += f[j].x * wv->x + f[j].y * wv->y + f[j].z * wv->z + f[j].w * wv->w;
        }
        P[(size_t)i * 9 + k] = a;
    }
}

__global__ __launch_bounds__(256)
void head_g(const float* __restrict__ P, const int* __restrict__ neigh,
            const float* __restrict__ b, float* __restrict__ out)
{
    int i = blockIdx.x * 256 + threadIdx.x;
    float acc = __ldg(b);
#pragma unroll
    for (int k = 0; k < 9; k++) {
        int n = __ldg(neigh + i * 9 + k);
        if (n >= 0) acc += __ldg(P + (size_t)n * 9 + k);
    }
    out[i] = acc;
}

static inline int cdiv(int a, int b) { return (a + b - 1) / b; }

extern "C" void kernel_launch(void* const* d_in, const int* in_sizes, int n_in,
                              void* d_out, int out_size)
{
    const float* features = (const float*)d_in[0];
    const int* neighs3 = (const int*)d_in[4];
    const int* neighs2 = (const int*)d_in[5];
    const int* neighs1 = (const int*)d_in[6];
    const float* w_enc1 = (const float*)d_in[7];
    const float* b_enc1 = (const float*)d_in[8];
    const float* w_enc2 = (const float*)d_in[9];
    const float* b_enc2 = (const float*)d_in[10];
    const float* w_enc3 = (const float*)d_in[11];
    const float* b_enc3 = (const float*)d_in[12];
    const float* w_dec1 = (const float*)d_in[13];
    const float* b_dec1 = (const float*)d_in[14];
    const float* w_dec2 = (const float*)d_in[15];
    const float* b_dec2 = (const float*)d_in[16];
    const float* w_head = (const float*)d_in[17];
    const float* b_head = (const float*)d_in[18];
    float* out = (float*)d_out;

    float *x8, *x7p, *x7, *x6p, *x6, *x7d, *x8d, *P;
    cudaGetSymbolAddress((void**)&x8,  g_x8);
    cudaGetSymbolAddress((void**)&x7p, g_x7p);
    cudaGetSymbolAddress((void**)&x7,  g_x7);
    cudaGetSymbolAddress((void**)&x6p, g_x6p);
    cudaGetSymbolAddress((void**)&x6,  g_x6);
    cudaGetSymbolAddress((void**)&x7d, g_x7d);
    cudaGetSymbolAddress((void**)&x8d, g_x8d);
    cudaGetSymbolAddress((void**)&P,   g_P);

    // dynamic smem: K*128*8 (dup A) + K*144*4 (B)
    const int SM16 = 16 * 128 * 8 + 16 * 144 * 4;   // 25600
    const int SM32 = 32 * 128 * 8 + 32 * 144 * 4;   // 51200
    const int SM64 = 64 * 128 * 8 + 64 * 144 * 4;   // 102400
    cudaFuncSetAttribute(gemm_k<16, 32>, cudaFuncAttributeMaxDynamicSharedMemorySize, SM16);
    cudaFuncSetAttribute(gemm_k<32, 64>, cudaFuncAttributeMaxDynamicSharedMemorySize, SM32);
    cudaFuncSetAttribute(gemm_k<64, 32>, cudaFuncAttributeMaxDynamicSharedMemorySize, SM64);
    cudaFuncSetAttribute(gemm_k<32, 16>, cudaFuncAttributeMaxDynamicSharedMemorySize, SM32);

    // enc1 (direct): [N3,1] -> x8 [N3,16]
    enc1_k<<<N3 / 256, 256>>>(features, neighs3, w_enc1, b_enc1, x8);
    // pool 3->2
    pool_k<16><<<cdiv(N2 * 16, 256), 256>>>(x8, x7p, N2);
    // enc2: P = x7p[N2,16] @ B[16,288]; gather -> x7 [N2,32]
    gemm_k<16, 32><<<dim3(N2 / 128, 2), 288, SM16>>>(x7p, w_enc2, P, 288);
    gather_k<32, 0, true><<<cdiv(N2, 256), 256>>>(P, neighs2, b_enc2, x7, N2);
    // pool 2->1
    pool_k<32><<<cdiv(N1 * 32, 256), 256>>>(x7, x6p, N1);
    // enc3: P = x6p[N1,32] @ B[32,576]; gather -> x6 [N1,64]
    gemm_k<32, 64><<<dim3(N1 / 128, 4), 288, SM32>>>(x6p, w_enc3, P, 576);
    gather_k<64, 0, true><<<cdiv(N1, 256), 256>>>(P, neighs1, b_enc3, x6, N1);
    // dec1: P = x6[N1,64] @ B[64,288]; gather(unpool >>2) -> x7d [N2,32]
    gemm_k<64, 32><<<dim3(N1 / 128, 2), 288, SM64>>>(x6, w_dec1, P, 288);
    gather_k<32, 2, true><<<cdiv(N2, 256), 256>>>(P, neighs2, b_dec1, x7d, N2);
    // dec2: P = x7d[N2,32] @ B[32,144]; gather(unpool >>2) -> x8d [N3,16]
    gemm_k<32, 16><<<dim3(N2 / 128, 1), 288, SM32>>>(x7d, w_dec2, P, 144);
    gather_k<16, 2, true><<<cdiv(N3, 256), 256>>>(P, neighs3, b_dec2, x8d, N3);
    // head: P6 = x8d @ w_head^T -> [N3,9]; scalar gather -> out [N3,1]
    head_p<<<N3 / 256, 256>>>(x8d, w_head, P);
    head_g<<<N3 / 256, 256>>>(P, neighs3, b_head, out);
}

// round 8
// speedup vs baseline: 2.3812x; 1.3822x over previous
#include <cuda_runtime.h>

#define N3 262144
#define N2 65536
#define N1 16384

typedef unsigned long long u64;

// ---------------- scratch (allocation-free) ----------------
__device__ float g_x7p[N2 * 16];
__device__ float g_x7 [N2 * 32];
__device__ float g_x6 [N1 * 64];
__device__ float g_x7d[N2 * 32];
__device__ float g_P  [N2 * 288];   // 75MB, reused by every P phase (max = enc2)
__device__ float g_P6 [N3 * 9];     // head partial products

__device__ __forceinline__ u64 pack2(float lo, float hi) {
    u64 r; asm("mov.b64 %0, {%1, %2};" : "=l"(r) : "f"(lo), "f"(hi)); return r;
}
__device__ __forceinline__ void fma2(u64& d, u64 a, u64 b) {
    asm("fma.rn.f32x2 %0, %1, %2, %0;" : "+l"(d) : "l"(a), "l"(b));
}
__device__ __forceinline__ float4 max4(float4 a, float4 b) {
    return make_float4(fmaxf(a.x,b.x), fmaxf(a.y,b.y), fmaxf(a.z,b.z), fmaxf(a.w,b.w));
}

// ---------------- GEMM: P[M x Ntot] = A[M x K] @ B[K x Ntot] ----------------
// B[c][g] = w[g%COUT][(g/COUT)*K + c]   (per-tap weight transpose, built in smem)
// APOOL: A row r = elementwise max of child rows 4r..4r+3 (fused quadpool; inputs >=0).
// Tile: TM=128 x TN=144, 288 threads, 8x8 per thread (f32x2 packed cols).
template<int K, int COUT, bool APOOL>
__global__ __launch_bounds__(288)
void gemm_k(const float* __restrict__ A, const float* __restrict__ w,
            float* __restrict__ P, int Ntot)
{
    extern __shared__ u64 sm64[];
    u64*   As2 = sm64;                       // [K][128] duplicated pairs (a,a)
    float* Bs  = (float*)(sm64 + K * 128);   // [K][144]

    const int tid  = threadIdx.x;
    const int row0 = blockIdx.x * 128;
    const int col0 = blockIdx.y * 144;

    // Stage A transposed + duplicated: As2[c][r] = (A[row0+r][c], same)
    // (A is always our own 16B-aligned scratch buffer -> float4 is safe)
    const float4* A4 = reinterpret_cast<const float4*>(A);
    const int KC4 = K / 4;
    for (int idx = tid; idx < 128 * KC4; idx += 288) {
        int r = idx / KC4, c4 = idx % KC4;
        float4 v;
        if (APOOL) {
            size_t base = (size_t)(row0 + r) * 4 * KC4 + c4;
            v = __ldg(A4 + base);
            v = max4(v, __ldg(A4 + base + KC4));
            v = max4(v, __ldg(A4 + base + 2 * KC4));
            v = max4(v, __ldg(A4 + base + 3 * KC4));
        } else {
            v = __ldg(A4 + (size_t)(row0 + r) * KC4 + c4);
        }
        As2[(c4 * 4 + 0) * 128 + r] = pack2(v.x, v.x);
        As2[(c4 * 4 + 1) * 128 + r] = pack2(v.y, v.y);
        As2[(c4 * 4 + 2) * 128 + r] = pack2(v.z, v.z);
        As2[(c4 * 4 + 3) * 128 + r] = pack2(v.w, v.w);
    }
    // Stage B with on-the-fly transpose of w (scalar loads: input buffer)
    for (int idx = tid; idx < K * 144; idx += 288) {
        int c = idx / 144, cl = idx % 144;
        int g = col0 + cl;
        Bs[c * 144 + cl] = __ldg(w + (g % COUT) * (9 * K) + (g / COUT) * K + c);
    }
    __syncthreads();

    const int tx = tid % 18;   // 18 col-groups of 8
    const int ty = tid / 18;   // 16 row-groups of 8

    u64 acc[8][4];
#pragma unroll
    for (int r = 0; r < 8; r++)
#pragma unroll
        for (int j = 0; j < 4; j++) acc[r][j] = 0ull;

#pragma unroll 4
    for (int kk = 0; kk < K; kk++) {
        const ulonglong2* ap = reinterpret_cast<const ulonglong2*>(&As2[kk * 128 + ty * 8]);
        ulonglong2 A0 = ap[0], A1 = ap[1], A2 = ap[2], A3 = ap[3];
        u64 a2[8] = {A0.x, A0.y, A1.x, A1.y, A2.x, A2.y, A3.x, A3.y};
        const ulonglong2* bp = reinterpret_cast<const ulonglong2*>(&Bs[kk * 144 + tx * 8]);
        ulonglong2 B0 = bp[0], B1 = bp[1];
        u64 b2[4] = {B0.x, B0.y, B1.x, B1.y};
#pragma unroll
        for (int r = 0; r < 8; r++)
#pragma unroll
            for (int j = 0; j < 4; j++)
                fma2(acc[r][j], a2[r], b2[j]);
    }

#pragma unroll
    for (int r = 0; r < 8; r++) {
        float* dst = P + (size_t)(row0 + ty * 8 + r) * Ntot + col0 + tx * 8;
        *reinterpret_cast<ulonglong2*>(dst)     = make_ulonglong2(acc[r][0], acc[r][1]);
        *reinterpret_cast<ulonglong2*>(dst + 4) = make_ulonglong2(acc[r][2], acc[r][3]);
    }
}

// ---------------- channel-parallel gather-sum ----------------
// thread = (node, 4 channels); COUT/4 consecutive threads cover a node's tap row
// -> each node-tap read is one contiguous COUT*4B transaction.
template<int COUT, int SHIFT, bool RELU>
__global__ __launch_bounds__(256)
void gather_k(const float* __restrict__ P, const int* __restrict__ neigh,
              const float* __restrict__ bias, float* __restrict__ out)
{
    constexpr int NPT = COUT / 4;     // threads per node
    constexpr int NPB = 256 / NPT;    // nodes per block
    __shared__ int sn[NPB * 9];
    const int node0 = blockIdx.x * NPB;
    for (int idx = threadIdx.x; idx < NPB * 9; idx += 256)
        sn[idx] = __ldg(neigh + (size_t)node0 * 9 + idx);
    __syncthreads();

    const int il = threadIdx.x / NPT, c4 = threadIdx.x % NPT;
    const int i = node0 + il;

    float4 v[9];
#pragma unroll
    for (int k = 0; k < 9; k++) {
        int n = sn[il * 9 + k];
        if (n >= 0)
            v[k] = __ldg(reinterpret_cast<const float4*>(
                       P + (size_t)(n >> SHIFT) * (9 * COUT) + k * COUT) + c4);
        else
            v[k] = make_float4(0.f, 0.f, 0.f, 0.f);
    }

    // bias: scalar loads (input buffer; avoid 16B-alignment assumption)
    float4 acc = make_float4(__ldg(bias + c4 * 4),     __ldg(bias + c4 * 4 + 1),
                             __ldg(bias + c4 * 4 + 2), __ldg(bias + c4 * 4 + 3));
#pragma unroll
    for (int k = 0; k < 9; k++) {
        acc.x += v[k].x; acc.y += v[k].y; acc.z += v[k].z; acc.w += v[k].w;
    }
    if (RELU) {
        acc.x = fmaxf(acc.x, 0.f); acc.y = fmaxf(acc.y, 0.f);
        acc.z = fmaxf(acc.z, 0.f); acc.w = fmaxf(acc.w, 0.f);
    }
    reinterpret_cast<float4*>(out + (size_t)i * COUT)[c4] = acc;
}

// ---------------- dec2 gather + fused head partial products ----------------
// COUT=16, SHIFT=2. Computes x8d slice in registers (relu), then the 9 head
// dots, butterfly-reduced over the node's 4 lanes; writes P6[i][0..8].
__global__ __launch_bounds__(256)
void gather_head_k(const float* __restrict__ P, const int* __restrict__ neigh,
                   const float* __restrict__ bias, const float* __restrict__ wh,
                   float* __restrict__ P6)
{
    constexpr int NPT = 4, NPB = 64;
    __shared__ int sn[NPB * 9];
    __shared__ float swh[144];
    const int node0 = blockIdx.x * NPB;
    for (int idx = threadIdx.x; idx < NPB * 9; idx += 256)
        sn[idx] = __ldg(neigh + (size_t)node0 * 9 + idx);
    if (threadIdx.x < 144) swh[threadIdx.x] = __ldg(wh + threadIdx.x);
    __syncthreads();

    const int il = threadIdx.x / NPT, c4 = threadIdx.x % NPT;
    const int i = node0 + il;

    float4 v[9];
#pragma unroll
    for (int k = 0; k < 9; k++) {
        int n = sn[il * 9 + k];
        if (n >= 0)
            v[k] = __ldg(reinterpret_cast<const float4*>(
                       P + (size_t)(n >> 2) * 144 + k * 16) + c4);
        else
            v[k] = make_float4(0.f, 0.f, 0.f, 0.f);
    }

    float4 acc = make_float4(__ldg(bias + c4 * 4),     __ldg(bias + c4 * 4 + 1),
                             __ldg(bias + c4 * 4 + 2), __ldg(bias + c4 * 4 + 3));
#pragma unroll
    for (int k = 0; k < 9; k++) {
        acc.x += v[k].x; acc.y += v[k].y; acc.z += v[k].z; acc.w += v[k].w;
    }
    acc.x = fmaxf(acc.x, 0.f); acc.y = fmaxf(acc.y, 0.f);
    acc.z = fmaxf(acc.z, 0.f); acc.w = fmaxf(acc.w, 0.f);

    // head partial dots: p[k2] = dot(acc, w_head[k2*16 + c4*4 .. +3])
    float p[9];
#pragma unroll
    for (int k2 = 0; k2 < 9; k2++) {
        const float* wv = &swh[k2 * 16 + c4 * 4];
        p[k2] = acc.x * wv[0] + acc.y * wv[1] + acc.z * wv[2] + acc.w * wv[3];
    }
    // butterfly across the 4 lanes of this node (lane groups are warp-aligned)
#pragma unroll
    for (int k2 = 0; k2 < 9; k2++) {
        p[k2] += __shfl_xor_sync(0xffffffffu, p[k2], 1);
        p[k2] += __shfl_xor_sync(0xffffffffu, p[k2], 2);
    }
    float* dst = P6 + (size_t)i * 9;
    dst[c4]     = p[c4];
    dst[c4 + 4] = p[c4 + 4];
    if (c4 == 0) dst[8] = p[8];
}

// ---------------- enc1 + pool3->2 fused: thread = parent node in N2 ----------------
__global__ __launch_bounds__(256)
void enc1pool_k(const float* __restrict__ feat, const int* __restrict__ neigh,
                const float* __restrict__ w, const float* __restrict__ b,
                float* __restrict__ out /* x7p [N2][16] */)
{
    __shared__ float sw[160];
    if (threadIdx.x < 144) sw[threadIdx.x] = __ldg(w + threadIdx.x);
    else if (threadIdx.x < 160) sw[threadIdx.x] = __ldg(b + threadIdx.x - 144);
    __syncthreads();

    int p = blockIdx.x * 256 + threadIdx.x;
    int nb[36];
#pragma unroll
    for (int j = 0; j < 36; j++) nb[j] = __ldg(neigh + (size_t)p * 36 + j);

    float m[16];
#pragma unroll
    for (int o = 0; o < 16; o++) m[o] = 0.f;   // relu(max(s)) with floor 0

#pragma unroll
    for (int ch = 0; ch < 4; ch++) {
        float f[9];
#pragma unroll
        for (int k = 0; k < 9; k++) {
            int n = nb[ch * 9 + k];
            f[k] = (n >= 0) ? __ldg(feat + n) : 0.f;
        }
#pragma unroll
        for (int o = 0; o < 16; o++) {
            float s = sw[144 + o];
#pragma unroll
            for (int k = 0; k < 9; k++) s += f[k] * sw[o * 9 + k];
            m[o] = fmaxf(m[o], s);
        }
    }
    float4* op = reinterpret_cast<float4*>(out + (size_t)p * 16);
#pragma unroll
    for (int j = 0; j < 4; j++)
        op[j] = make_float4(m[4*j], m[4*j+1], m[4*j+2], m[4*j+3]);
}

// ---------------- head gather: out[i] = b + sum_k P6[n_k][k] ----------------
__global__ __launch_bounds__(256)
void head_g(const float* __restrict__ P6, const int* __restrict__ neigh,
            const float* __restrict__ b, float* __restrict__ out)
{
    int i = blockIdx.x * 256 + threadIdx.x;
    float acc = __ldg(b);
#pragma unroll
    for (int k = 0; k < 9; k++) {
        int n = __ldg(neigh + (size_t)i * 9 + k);
        if (n >= 0) acc += __ldg(P6 + (size_t)n * 9 + k);
    }
    out[i] = acc;
}

extern "C" void kernel_launch(void* const* d_in, const int* in_sizes, int n_in,
                              void* d_out, int out_size)
{
    const float* features = (const float*)d_in[0];
    const int* neighs3 = (const int*)d_in[4];
    const int* neighs2 = (const int*)d_in[5];
    const int* neighs1 = (const int*)d_in[6];
    const float* w_enc1 = (const float*)d_in[7];
    const float* b_enc1 = (const float*)d_in[8];
    const float* w_enc2 = (const float*)d_in[9];
    const float* b_enc2 = (const float*)d_in[10];
    const float* w_enc3 = (const float*)d_in[11];
    const float* b_enc3 = (const float*)d_in[12];
    const float* w_dec1 = (const float*)d_in[13];
    const float* b_dec1 = (const float*)d_in[14];
    const float* w_dec2 = (const float*)d_in[15];
    const float* b_dec2 = (const float*)d_in[16];
    const float* w_head = (const float*)d_in[17];
    const float* b_head = (const float*)d_in[18];
    float* out = (float*)d_out;

    float *x7p, *x7, *x6, *x7d, *P, *P6;
    cudaGetSymbolAddress((void**)&x7p, g_x7p);
    cudaGetSymbolAddress((void**)&x7,  g_x7);
    cudaGetSymbolAddress((void**)&x6,  g_x6);
    cudaGetSymbolAddress((void**)&x7d, g_x7d);
    cudaGetSymbolAddress((void**)&P,   g_P);
    cudaGetSymbolAddress((void**)&P6,  g_P6);

    // dynamic smem: K*128*8 (dup A) + K*144*4 (B)
    const int SM16 = 16 * 128 * 8 + 16 * 144 * 4;   // 25600
    const int SM32 = 32 * 128 * 8 + 32 * 144 * 4;   // 51200
    const int SM64 = 64 * 128 * 8 + 64 * 144 * 4;   // 102400
    cudaFuncSetAttribute(gemm_k<16, 32, false>, cudaFuncAttributeMaxDynamicSharedMemorySize, SM16);
    cudaFuncSetAttribute(gemm_k<32, 64, true>,  cudaFuncAttributeMaxDynamicSharedMemorySize, SM32);
    cudaFuncSetAttribute(gemm_k<64, 32, false>, cudaFuncAttributeMaxDynamicSharedMemorySize, SM64);
    cudaFuncSetAttribute(gemm_k<32, 16, false>, cudaFuncAttributeMaxDynamicSharedMemorySize, SM32);

    // enc1 + pool3->2 fused: features [N3,1] -> x7p [N2,16]
    enc1pool_k<<<N2 / 256, 256>>>(features, neighs3, w_enc1, b_enc1, x7p);
    // enc2: P = x7p[N2,16] @ B[16,288]; gather -> x7 [N2,32]
    gemm_k<16, 32, false><<<dim3(N2 / 128, 2), 288, SM16>>>(x7p, w_enc2, P, 288);
    gather_k<32, 0, true><<<N2 / 32, 256>>>(P, neighs2, b_enc2, x7);
    // enc3 (pool2->1 fused into A-stage): P = pool(x7)[N1,32] @ B[32,576]; gather -> x6 [N1,64]
    gemm_k<32, 64, true><<<dim3(N1 / 128, 4), 288, SM32>>>(x7, w_enc3, P, 576);
    gather_k<64, 0, true><<<N1 / 16, 256>>>(P, neighs1, b_enc3, x6);
    // dec1: P = x6[N1,64] @ B[64,288]; gather(unpool >>2) -> x7d [N2,32]
    gemm_k<64, 32, false><<<dim3(N1 / 128, 2), 288, SM64>>>(x6, w_dec1, P, 288);
    gather_k<32, 2, true><<<N2 / 32, 256>>>(P, neighs2, b_dec1, x7d);
    // dec2: P = x7d[N2,32] @ B[32,144]; gather(unpool >>2) + fused head dots -> P6 [N3,9]
    gemm_k<32, 16, false><<<dim3(N2 / 128, 1), 288, SM32>>>(x7d, w_dec2, P, 144);
    gather_head_k<<<N3 / 64, 256>>>(P, neighs3, b_dec2, w_head, P6);
    // head gather -> out [N3,1]
    head_g<<<N3 / 256, 256>>>(P6, neighs3, b_head, out);
}